// round 6
// baseline (speedup 1.0000x reference)
#include <cuda_runtime.h>

// EvolvingGNN: T=5, N=100000, E=1600000, D=H=64, FE=16.
//  (1) Only xs_out[-1] is consumed -> one GCN pass with the LSTM weight after 5 steps.
//  (2) Edge MLP factors: hid = relu(A[src] + B[dst] + ea@W1c + b1).
//  (3) LSTM: 5 steps inside one launch (block r owns W column r == h row r).
//  (4) Aggregation: float4 vector atomics (RED.128) -- measured faster than CSR gather (R4).
//  (5) Edge MLP: persistent warps, register-resident Wc/b1/w2 amortized over ~170 edges/warp.
// edge_index arrives as int32 (JAX x64-disabled downgrades jnp.int64).

#define NMAX 100000

__device__ float g_Wt[64 * 64];        // final evolved weight, [k][r]
__device__ int   g_cnt[NMAX];          // in-degree (excl self loop)
__device__ float g_dinv[NMAX];
__device__ float g_xws[NMAX * 64];     // dinv[n] * (xs[4] @ W)[n]
__device__ float g_agg[NMAX * 64];     // GCN aggregation (pre-relu)
__device__ float g_A[NMAX * 64];       // relu(agg) @ W1[0:64]
__device__ float g_B[NMAX * 64];       // relu(agg) @ W1[64:128]

__device__ __forceinline__ float sigmoidf(float x) { return 1.0f / (1.0f + expf(-x)); }

// ---------------- LSTM: all 5 steps in one launch ----------------
__global__ void lstm_all_kernel(const float* __restrict__ w0,
                                const float* __restrict__ w_ih,
                                const float* __restrict__ w_hh,
                                const float* __restrict__ b_ih,
                                const float* __restrict__ b_hh) {
    __shared__ float xb[64], cr[64], gate[256];
    int r = blockIdx.x;
    int tid = threadIdx.x;
    if (tid < 64) {
        xb[tid] = w0[tid * 64 + r];
        cr[tid] = 0.f;
    }
    float bsum = b_ih[tid] + b_hh[tid];
    const float4* wi = (const float4*)(w_ih + tid * 64);
    const float4* wh = (const float4*)(w_hh + tid * 64);
    for (int t = 0; t < 5; t++) {
        __syncthreads();
        float acc = bsum;
#pragma unroll
        for (int k4 = 0; k4 < 16; k4++) {
            float4 a = wi[k4];
            float4 b = wh[k4];
            float x0 = xb[4 * k4], x1 = xb[4 * k4 + 1], x2 = xb[4 * k4 + 2], x3 = xb[4 * k4 + 3];
            acc += a.x * x0 + a.y * x1 + a.z * x2 + a.w * x3;
            if (t > 0)   // hidden state == previous output column for t>=1; 0 at t==0
                acc += b.x * x0 + b.y * x1 + b.z * x2 + b.w * x3;
        }
        gate[tid] = acc;
        __syncthreads();
        if (tid < 64) {
            float gi = sigmoidf(gate[tid]);
            float gf = sigmoidf(gate[64 + tid]);
            float gg = tanhf(gate[128 + tid]);
            float go = sigmoidf(gate[192 + tid]);
            float cn = gf * cr[tid] + gi * gg;
            float hn = go * tanhf(cn);
            cr[tid] = cn;
            xb[tid] = hn;
        }
    }
    if (tid < 64) g_Wt[tid * 64 + r] = xb[tid];
}

// ---------------- Degree / normalization ----------------
__global__ void zero_cnt_kernel(int n) {
    int i = blockIdx.x * blockDim.x + threadIdx.x;
    if (i < n) g_cnt[i] = 0;
}
__global__ void deg_count_kernel(const int* __restrict__ ei, int E) {
    int e = blockIdx.x * blockDim.x + threadIdx.x;
    if (e < E) atomicAdd(&g_cnt[ei[E + e]], 1);
}
__global__ void dinv_kernel(int n) {
    int i = blockIdx.x * blockDim.x + threadIdx.x;
    if (i < n) g_dinv[i] = rsqrtf((float)g_cnt[i] + 1.0f);   // +1 = self loop
}

// ---------------- xws = dinv*(xs[last] @ W); agg = dinv*xws (self-loop init) ----------------
__global__ void xw_kernel(const float* __restrict__ x, int n) {
    __shared__ float Ws[64 * 64];
    __shared__ float Xs[16 * 64];
    int tid = threadIdx.x;
    for (int i = tid; i < 4096; i += 256) Ws[i] = g_Wt[i];
    int row0 = blockIdx.x * 16;
    for (int i = tid; i < 1024; i += 256) {
        int rr = i >> 6, cc = i & 63;
        int nn = row0 + rr;
        Xs[i] = (nn < n) ? x[(size_t)nn * 64 + cc] : 0.f;
    }
    __syncthreads();
    int jr = (tid & 15) * 4;
    int rr = tid >> 4;
    float a0 = 0, a1 = 0, a2 = 0, a3 = 0;
    const float* xr = Xs + rr * 64;
#pragma unroll 8
    for (int k = 0; k < 64; k++) {
        float xv = xr[k];
        const float* wk = Ws + k * 64 + jr;
        a0 += xv * wk[0]; a1 += xv * wk[1]; a2 += xv * wk[2]; a3 += xv * wk[3];
    }
    int nn = row0 + rr;
    if (nn < n) {
        float dv = g_dinv[nn];
        float4 s = make_float4(dv * a0, dv * a1, dv * a2, dv * a3);
        *(float4*)(g_xws + (size_t)nn * 64 + jr) = s;
        *(float4*)(g_agg + (size_t)nn * 64 + jr) =
            make_float4(dv * s.x, dv * s.y, dv * s.z, dv * s.w);
    }
}

// ---------------- edge scatter: agg[dst] += dinv[dst] * xws[src] ----------------
// 16 lanes per edge, float4 gather + float4 vector atomic (RED.128, no return).
__global__ void scatter_kernel(const int* __restrict__ ei, int E) {
    int idx = blockIdx.x * blockDim.x + threadIdx.x;
    int e = idx >> 4;
    int l = idx & 15;
    if (e >= E) return;
    int src = ei[e];
    int dst = ei[E + e];
    float coef = g_dinv[dst];
    float4 v = *(const float4*)(g_xws + (size_t)src * 64 + 4 * l);
    float4 m = make_float4(coef * v.x, coef * v.y, coef * v.z, coef * v.w);
    atomicAdd((float4*)(g_agg + (size_t)dst * 64 + 4 * l), m);
}

// ---------------- A,B = relu(agg) @ W1[0:64], @ W1[64:128] ----------------
__global__ void ab_kernel(const float* __restrict__ w1, int n) {
    __shared__ float Wa[64 * 64];
    __shared__ float Wb[64 * 64];
    __shared__ float Xs[16 * 64];
    int tid = threadIdx.x;
    for (int i = tid; i < 4096; i += 256) { Wa[i] = w1[i]; Wb[i] = w1[4096 + i]; }
    int row0 = blockIdx.x * 16;
    for (int i = tid; i < 1024; i += 256) {
        int rr = i >> 6, cc = i & 63;
        int nn = row0 + rr;
        Xs[i] = (nn < n) ? fmaxf(g_agg[(size_t)nn * 64 + cc], 0.f) : 0.f;   // relu
    }
    __syncthreads();
    int jr = (tid & 15) * 4;
    int rr = tid >> 4;
    float a0 = 0, a1 = 0, a2 = 0, a3 = 0;
    float b0 = 0, b1v = 0, b2v = 0, b3 = 0;
    const float* xr = Xs + rr * 64;
#pragma unroll 4
    for (int k = 0; k < 64; k++) {
        float xv = xr[k];
        const float* wa = Wa + k * 64 + jr;
        const float* wb = Wb + k * 64 + jr;
        a0 += xv * wa[0]; a1 += xv * wa[1]; a2 += xv * wa[2]; a3 += xv * wa[3];
        b0 += xv * wb[0]; b1v += xv * wb[1]; b2v += xv * wb[2]; b3 += xv * wb[3];
    }
    int nn = row0 + rr;
    if (nn < n) {
        *(float4*)(g_A + (size_t)nn * 64 + jr) = make_float4(a0, a1, a2, a3);
        *(float4*)(g_B + (size_t)nn * 64 + jr) = make_float4(b0, b1v, b2v, b3);
    }
}

// ---------------- Edge MLP: persistent warps, registers amortized over many edges ----------
// logit = relu(A[src]+B[dst]+ea@W1c+b1) . w2 + b2
// Lanes 0-15 load A chunk (float4), lanes 16-31 load B chunk; shfl_xor(16) exchange.
__global__ void edge_mlp_kernel(const int* __restrict__ ei,
                                const float* __restrict__ ea,
                                const float* __restrict__ w1,
                                const float* __restrict__ b1,
                                const float* __restrict__ w2,
                                const float* __restrict__ b2,
                                float* __restrict__ out, int E) {
    int tid = threadIdx.x;
    int lane = tid & 31;
    int half = lane & 15;
    bool hiB = lane >= 16;
    int j0 = half * 4 + (hiB ? 2 : 0);          // this lane's two hidden dims: j0, j0+1
    float wc0[16], wc1[16];
#pragma unroll
    for (int k = 0; k < 16; k++) {
        wc0[k] = w1[8192 + k * 64 + j0];
        wc1[k] = w1[8192 + k * 64 + j0 + 1];
    }
    float bb0 = b1[j0], bb1 = b1[j0 + 1];
    float ww0 = w2[j0], ww1 = w2[j0 + 1];
    float b2v = b2[0];

    int warp = (blockIdx.x * blockDim.x + tid) >> 5;
    int nwarps = (gridDim.x * blockDim.x) >> 5;

    for (int e = warp; e < E; e += nwarps) {
        int src = ei[e];
        int dst = ei[E + e];
        float4 mine = hiB ? ((const float4*)g_B)[(size_t)dst * 16 + half]
                          : ((const float4*)g_A)[(size_t)src * 16 + half];
        float4 other;
        other.x = __shfl_xor_sync(0xffffffffu, mine.x, 16);
        other.y = __shfl_xor_sync(0xffffffffu, mine.y, 16);
        other.z = __shfl_xor_sync(0xffffffffu, mine.z, 16);
        other.w = __shfl_xor_sync(0xffffffffu, mine.w, 16);
        float h0, h1;
        if (hiB) {
            h0 = mine.z + other.z + bb0;
            h1 = mine.w + other.w + bb1;
        } else {
            h0 = mine.x + other.x + bb0;
            h1 = mine.y + other.y + bb1;
        }
        float eav = (lane < 16) ? ea[(size_t)e * 16 + lane] : 0.f;
#pragma unroll
        for (int k = 0; k < 16; k++) {
            float ek = __shfl_sync(0xffffffffu, eav, k);
            h0 += ek * wc0[k];
            h1 += ek * wc1[k];
        }
        h0 = fmaxf(h0, 0.f);
        h1 = fmaxf(h1, 0.f);
        float p = h0 * ww0 + h1 * ww1;
#pragma unroll
        for (int off = 16; off; off >>= 1) p += __shfl_xor_sync(0xffffffffu, p, off);
        if (lane == 0) out[e] = p + b2v;
    }
}

extern "C" void kernel_launch(void* const* d_in, const int* in_sizes, int n_in,
                              void* d_out, int out_size) {
    const float* xs = (const float*)d_in[0];
    const int* ei = (const int*)d_in[1];            // int32 (JAX x64 disabled)
    const float* ea = (const float*)d_in[2];
    const float* init_w = (const float*)d_in[3];
    const float* w_ih = (const float*)d_in[4];
    const float* w_hh = (const float*)d_in[5];
    const float* b_ih = (const float*)d_in[6];
    const float* b_hh = (const float*)d_in[7];
    const float* w1 = (const float*)d_in[8];
    const float* b1 = (const float*)d_in[9];
    const float* w2 = (const float*)d_in[10];
    const float* b2 = (const float*)d_in[11];
    float* out = (float*)d_out;

    int N = in_sizes[0] / (5 * 64);
    int E = in_sizes[1] / 2;

    // 1) LSTM weight evolution (single launch)
    lstm_all_kernel<<<64, 256>>>(init_w, w_ih, w_hh, b_ih, b_hh);

    // 2) GCN normalization
    zero_cnt_kernel<<<(N + 255) / 256, 256>>>(N);
    deg_count_kernel<<<(E + 255) / 256, 256>>>(ei, E);
    dinv_kernel<<<(N + 255) / 256, 256>>>(N);

    // 3) xws = dinv * (xs[4] @ W), agg initialized with self-loop term
    xw_kernel<<<(N + 15) / 16, 256>>>(xs + (size_t)4 * N * 64, N);

    // 4) edge scatter with float4 vector atomics
    scatter_kernel<<<(E * 16 + 255) / 256, 256>>>(ei, E);

    // 5) per-node MLP halves
    ab_kernel<<<(N + 15) / 16, 256>>>(w1, N);

    // 6) per-edge MLP + logit (persistent warps)
    edge_mlp_kernel<<<1184, 256>>>(ei, ea, w1, b1, w2, b2, out, E);
}

// round 7
// speedup vs baseline: 1.1376x; 1.1376x over previous
#include <cuda_runtime.h>

// EvolvingGNN: T=5, N=100000, E=1600000, D=H=64, FE=16.
//  (1) Only xs_out[-1] is consumed -> one GCN pass with the LSTM weight after 5 steps.
//  (2) Edge MLP factors: hid = relu(A[src] + B[dst] + ea@W1c + b1).
//  (3) LSTM: 5 steps inside one launch; fused with cnt zeroing (heterogeneous grid).
//  (4) Aggregation: float4 vector atomics (RED.128).
//  (5) Edge MLP: R3 shared-memory version (best measured).
// Launch order puts scatter_kernel at position #4 for ncu profiling.
// edge_index arrives as int32 (JAX x64-disabled downgrades jnp.int64).

#define NMAX 100000

__device__ float g_Wt[64 * 64];        // final evolved weight, [k][r]
__device__ int   g_cnt[NMAX];          // in-degree (excl self loop)
__device__ float g_dinv[NMAX];
__device__ float g_xws[NMAX * 64];     // dinv[n] * (xs[4] @ W)[n]
__device__ float g_agg[NMAX * 64];     // GCN aggregation (pre-relu)
__device__ float g_A[NMAX * 64];       // relu(agg) @ W1[0:64]
__device__ float g_B[NMAX * 64];       // relu(agg) @ W1[64:128]

__device__ __forceinline__ float sigmoidf(float x) { return 1.0f / (1.0f + expf(-x)); }

// ---------------- k1: LSTM (blocks 0..63) + zero g_cnt (blocks 64..) ----------------
__global__ void lstm_zero_kernel(const float* __restrict__ w0,
                                 const float* __restrict__ w_ih,
                                 const float* __restrict__ w_hh,
                                 const float* __restrict__ b_ih,
                                 const float* __restrict__ b_hh,
                                 int n) {
    if (blockIdx.x >= 64) {
        int i = (blockIdx.x - 64) * 256 + threadIdx.x;
        if (i < n) g_cnt[i] = 0;
        return;
    }
    __shared__ float xb[64], cr[64], gate[256];
    int r = blockIdx.x;
    int tid = threadIdx.x;
    if (tid < 64) {
        xb[tid] = w0[tid * 64 + r];
        cr[tid] = 0.f;
    }
    float bsum = b_ih[tid] + b_hh[tid];
    const float4* wi = (const float4*)(w_ih + tid * 64);
    const float4* wh = (const float4*)(w_hh + tid * 64);
    for (int t = 0; t < 5; t++) {
        __syncthreads();
        float acc = bsum;
#pragma unroll
        for (int k4 = 0; k4 < 16; k4++) {
            float4 a = wi[k4];
            float4 b = wh[k4];
            float x0 = xb[4 * k4], x1 = xb[4 * k4 + 1], x2 = xb[4 * k4 + 2], x3 = xb[4 * k4 + 3];
            acc += a.x * x0 + a.y * x1 + a.z * x2 + a.w * x3;
            if (t > 0)   // hidden state == previous output column for t>=1; 0 at t==0
                acc += b.x * x0 + b.y * x1 + b.z * x2 + b.w * x3;
        }
        gate[tid] = acc;
        __syncthreads();
        if (tid < 64) {
            float gi = sigmoidf(gate[tid]);
            float gf = sigmoidf(gate[64 + tid]);
            float gg = tanhf(gate[128 + tid]);
            float go = sigmoidf(gate[192 + tid]);
            float cn = gf * cr[tid] + gi * gg;
            float hn = go * tanhf(cn);
            cr[tid] = cn;
            xb[tid] = hn;
        }
    }
    if (tid < 64) g_Wt[tid * 64 + r] = xb[tid];
}

// ---------------- k2: in-degree histogram ----------------
__global__ void deg_count_kernel(const int* __restrict__ ei, int E) {
    int e = blockIdx.x * blockDim.x + threadIdx.x;
    if (e < E) atomicAdd(&g_cnt[ei[E + e]], 1);
}

// ---------------- k3: xws = dinv*(xs[4] @ W); agg = dinv*xws; dinv computed inline ----------
__global__ void xw_kernel(const float* __restrict__ x, int n) {
    __shared__ float Ws[64 * 64];
    __shared__ float Xs[16 * 64];
    int tid = threadIdx.x;
    for (int i = tid; i < 4096; i += 256) Ws[i] = g_Wt[i];
    int row0 = blockIdx.x * 16;
    for (int i = tid; i < 1024; i += 256) {
        int rr = i >> 6, cc = i & 63;
        int nn = row0 + rr;
        Xs[i] = (nn < n) ? x[(size_t)nn * 64 + cc] : 0.f;
    }
    __syncthreads();
    int jr = (tid & 15) * 4;
    int rr = tid >> 4;
    float a0 = 0, a1 = 0, a2 = 0, a3 = 0;
    const float* xr = Xs + rr * 64;
#pragma unroll 8
    for (int k = 0; k < 64; k++) {
        float xv = xr[k];
        const float* wk = Ws + k * 64 + jr;
        a0 += xv * wk[0]; a1 += xv * wk[1]; a2 += xv * wk[2]; a3 += xv * wk[3];
    }
    int nn = row0 + rr;
    if (nn < n) {
        float dv = rsqrtf((float)g_cnt[nn] + 1.0f);   // +1 = self loop
        if ((tid & 15) == 0) g_dinv[nn] = dv;
        float4 s = make_float4(dv * a0, dv * a1, dv * a2, dv * a3);
        *(float4*)(g_xws + (size_t)nn * 64 + jr) = s;
        *(float4*)(g_agg + (size_t)nn * 64 + jr) =
            make_float4(dv * s.x, dv * s.y, dv * s.z, dv * s.w);
    }
}

// ---------------- k4 (PROFILED): edge scatter agg[dst] += dinv[dst] * xws[src] ----------
// 16 lanes per edge, float4 gather + float4 vector atomic (RED.128, no return).
__global__ void scatter_kernel(const int* __restrict__ ei, int E) {
    int idx = blockIdx.x * blockDim.x + threadIdx.x;
    int e = idx >> 4;
    int l = idx & 15;
    if (e >= E) return;
    int src = ei[e];
    int dst = ei[E + e];
    float coef = g_dinv[dst];
    float4 v = *(const float4*)(g_xws + (size_t)src * 64 + 4 * l);
    float4 m = make_float4(coef * v.x, coef * v.y, coef * v.z, coef * v.w);
    atomicAdd((float4*)(g_agg + (size_t)dst * 64 + 4 * l), m);
}

// ---------------- k5: A,B = relu(agg) @ W1[0:64], @ W1[64:128] ----------------
__global__ void ab_kernel(const float* __restrict__ w1, int n) {
    __shared__ float Wa[64 * 64];
    __shared__ float Wb[64 * 64];
    __shared__ float Xs[16 * 64];
    int tid = threadIdx.x;
    for (int i = tid; i < 4096; i += 256) { Wa[i] = w1[i]; Wb[i] = w1[4096 + i]; }
    int row0 = blockIdx.x * 16;
    for (int i = tid; i < 1024; i += 256) {
        int rr = i >> 6, cc = i & 63;
        int nn = row0 + rr;
        Xs[i] = (nn < n) ? fmaxf(g_agg[(size_t)nn * 64 + cc], 0.f) : 0.f;   // relu
    }
    __syncthreads();
    int jr = (tid & 15) * 4;
    int rr = tid >> 4;
    float a0 = 0, a1 = 0, a2 = 0, a3 = 0;
    float b0 = 0, b1v = 0, b2v = 0, b3 = 0;
    const float* xr = Xs + rr * 64;
#pragma unroll 4
    for (int k = 0; k < 64; k++) {
        float xv = xr[k];
        const float* wa = Wa + k * 64 + jr;
        const float* wb = Wb + k * 64 + jr;
        a0 += xv * wa[0]; a1 += xv * wa[1]; a2 += xv * wa[2]; a3 += xv * wa[3];
        b0 += xv * wb[0]; b1v += xv * wb[1]; b2v += xv * wb[2]; b3 += xv * wb[3];
    }
    int nn = row0 + rr;
    if (nn < n) {
        *(float4*)(g_A + (size_t)nn * 64 + jr) = make_float4(a0, a1, a2, a3);
        *(float4*)(g_B + (size_t)nn * 64 + jr) = make_float4(b0, b1v, b2v, b3);
    }
}

// ---------------- k6: Edge MLP (R3 version): relu(A[src]+B[dst]+ea@W1c+b1).w2 + b2 -------
// One warp per edge; lane handles hid[2*lane], hid[2*lane+1] via float2 loads.
__global__ void edge_mlp_kernel(const int* __restrict__ ei,
                                const float* __restrict__ ea,
                                const float* __restrict__ w1,
                                const float* __restrict__ b1,
                                const float* __restrict__ w2,
                                const float* __restrict__ b2,
                                float* __restrict__ out, int E) {
    __shared__ float Wc[16 * 64];
    __shared__ float b1s[64];
    __shared__ float w2s[64];
    __shared__ float b2s;
    int tid = threadIdx.x;
    for (int i = tid; i < 1024; i += 256) Wc[i] = w1[8192 + i];   // rows 128..143
    if (tid < 64) { b1s[tid] = b1[tid]; w2s[tid] = w2[tid]; }
    if (tid == 0) b2s = b2[0];
    __syncthreads();
    int e = (blockIdx.x * 256 + tid) >> 5;
    int lane = tid & 31;
    if (e >= E) return;
    int src = ei[e];
    int dst = ei[E + e];
    float2 av = *(const float2*)(g_A + (size_t)src * 64 + 2 * lane);
    float2 bv = *(const float2*)(g_B + (size_t)dst * 64 + 2 * lane);
    float h0 = av.x + bv.x + b1s[2 * lane];
    float h1 = av.y + bv.y + b1s[2 * lane + 1];
    float eav = (lane < 16) ? ea[(size_t)e * 16 + lane] : 0.f;
#pragma unroll
    for (int k = 0; k < 16; k++) {
        float ek = __shfl_sync(0xffffffffu, eav, k);
        float2 wv = *(const float2*)(Wc + k * 64 + 2 * lane);
        h0 += ek * wv.x;
        h1 += ek * wv.y;
    }
    h0 = fmaxf(h0, 0.f);
    h1 = fmaxf(h1, 0.f);
    float p = h0 * w2s[2 * lane] + h1 * w2s[2 * lane + 1];
#pragma unroll
    for (int off = 16; off; off >>= 1) p += __shfl_xor_sync(0xffffffffu, p, off);
    if (lane == 0) out[e] = p + b2s;
}

extern "C" void kernel_launch(void* const* d_in, const int* in_sizes, int n_in,
                              void* d_out, int out_size) {
    const float* xs = (const float*)d_in[0];
    const int* ei = (const int*)d_in[1];            // int32 (JAX x64 disabled)
    const float* ea = (const float*)d_in[2];
    const float* init_w = (const float*)d_in[3];
    const float* w_ih = (const float*)d_in[4];
    const float* w_hh = (const float*)d_in[5];
    const float* b_ih = (const float*)d_in[6];
    const float* b_hh = (const float*)d_in[7];
    const float* w1 = (const float*)d_in[8];
    const float* b1 = (const float*)d_in[9];
    const float* w2 = (const float*)d_in[10];
    const float* b2 = (const float*)d_in[11];
    float* out = (float*)d_out;

    int N = in_sizes[0] / (5 * 64);
    int E = in_sizes[1] / 2;

    // k1: LSTM + zero cnt (heterogeneous grid)
    lstm_zero_kernel<<<64 + (N + 255) / 256, 256>>>(init_w, w_ih, w_hh, b_ih, b_hh, N);
    // k2: in-degree histogram
    deg_count_kernel<<<(E + 255) / 256, 256>>>(ei, E);
    // k3: xws + agg self-loop init (dinv inline)
    xw_kernel<<<(N + 15) / 16, 256>>>(xs + (size_t)4 * N * 64, N);
    // k4: edge scatter (profiled slot)
    scatter_kernel<<<(E * 16 + 255) / 256, 256>>>(ei, E);
    // k5: per-node MLP halves
    ab_kernel<<<(N + 15) / 16, 256>>>(w1, N);
    // k6: per-edge MLP + logit
    edge_mlp_kernel<<<(E + 7) / 8, 256>>>(ei, ea, w1, b1, w2, b2, out, E);
}

// round 8
// speedup vs baseline: 1.1865x; 1.0430x over previous
#include <cuda_runtime.h>

// EvolvingGNN: T=5, N=100000, E=1600000, D=H=64, FE=16.
//  (1) Only xs_out[-1] is consumed -> one GCN pass with the LSTM weight after 5 steps.
//  (2) (P@X)@W == P@(X@W): aggregate raw X first, apply W after -> fused triple GEMM.
//  (3) Edge MLP factors: hid = relu(A[src] + B[dst] + ea@W1c + b1).
//  (4) Cross-call invariant: g_cnt/g_aggx zeroed by tail blocks of k4 (zero-init at load).
//  Launch order: k1 lstm+deg, k2 scatter_x, k3 gemm_AB, k4 edge_mlp (profiled slot #4).
// edge_index arrives as int32 (JAX x64-disabled downgrades jnp.int64).

#define NMAX 100000

__device__ float g_Wt[64 * 64];        // final evolved weight, [k][r]
__device__ int   g_cnt[NMAX];          // in-degree (excl self loop); zeroed by prev call
__device__ float g_aggx[NMAX * 64];    // normAdj @ X; zeroed by prev call
__device__ float g_A[NMAX * 64];       // relu(aggx@W) @ W1[0:64]
__device__ float g_B[NMAX * 64];       // relu(aggx@W) @ W1[64:128]

__device__ __forceinline__ float sigmoidf(float x) { return 1.0f / (1.0f + expf(-x)); }

// ---------------- k1: LSTM (blocks 0..63) + in-degree histogram (blocks 64..) ----------
__global__ void lstm_deg_kernel(const float* __restrict__ w0,
                                const float* __restrict__ w_ih,
                                const float* __restrict__ w_hh,
                                const float* __restrict__ b_ih,
                                const float* __restrict__ b_hh,
                                const int* __restrict__ ei, int E) {
    if (blockIdx.x >= 64) {
        int e = (blockIdx.x - 64) * 256 + threadIdx.x;
        if (e < E) atomicAdd(&g_cnt[ei[E + e]], 1);
        return;
    }
    __shared__ float xb[64], cr[64], gate[256];
    int r = blockIdx.x;
    int tid = threadIdx.x;
    if (tid < 64) {
        xb[tid] = w0[tid * 64 + r];
        cr[tid] = 0.f;
    }
    float bsum = b_ih[tid] + b_hh[tid];
    const float4* wi = (const float4*)(w_ih + tid * 64);
    const float4* wh = (const float4*)(w_hh + tid * 64);
    for (int t = 0; t < 5; t++) {
        __syncthreads();
        float acc = bsum;
#pragma unroll
        for (int k4 = 0; k4 < 16; k4++) {
            float4 a = wi[k4];
            float4 b = wh[k4];
            float x0 = xb[4 * k4], x1 = xb[4 * k4 + 1], x2 = xb[4 * k4 + 2], x3 = xb[4 * k4 + 3];
            acc += a.x * x0 + a.y * x1 + a.z * x2 + a.w * x3;
            if (t > 0)   // hidden state == previous output column for t>=1; 0 at t==0
                acc += b.x * x0 + b.y * x1 + b.z * x2 + b.w * x3;
        }
        gate[tid] = acc;
        __syncthreads();
        if (tid < 64) {
            float gi = sigmoidf(gate[tid]);
            float gf = sigmoidf(gate[64 + tid]);
            float gg = tanhf(gate[128 + tid]);
            float go = sigmoidf(gate[192 + tid]);
            float cn = gf * cr[tid] + gi * gg;
            float hn = go * tanhf(cn);
            cr[tid] = cn;
            xb[tid] = hn;
        }
    }
    if (tid < 64) g_Wt[tid * 64 + r] = xb[tid];
}

// ---------------- k2: scatter raw X: aggx[dst] += coef * x[src]; items = E edges + N loops
// 16 lanes per item, float4 gather + float4 vector atomic. coef computed by one lane
// per item (rsqrt of degree product) and shfl-broadcast.
__global__ void scatter_x_kernel(const float* __restrict__ x,
                                 const int* __restrict__ ei, int N, int E) {
    int idx = blockIdx.x * 256 + threadIdx.x;
    int item = idx >> 4;
    int l = idx & 15;
    int lane = threadIdx.x & 31;
    int total = E + N;
    bool active = item < total;
    int src = 0, dst = 0;
    if (active) {
        if (item < E) { src = ei[item]; dst = ei[E + item]; }
        else          { src = dst = item - E; }
    }
    float c = 0.f;
    if ((lane & 15) == 0) {
        float ps = (float)(g_cnt[src] + 1);
        float pd = (float)(g_cnt[dst] + 1);
        c = rsqrtf(ps * pd);
    }
    c = __shfl_sync(0xffffffffu, c, lane & 16);
    if (active) {
        float4 v = *(const float4*)(x + (size_t)src * 64 + 4 * l);
        atomicAdd((float4*)(g_aggx + (size_t)dst * 64 + 4 * l),
                  make_float4(c * v.x, c * v.y, c * v.z, c * v.w));
    }
}

// ---------------- k3: Y = relu(aggx @ W);  A = Y@W1a;  B = Y@W1b  (per 16-node tile) ----
__global__ void gemm_AB_kernel(const float* __restrict__ w1, int n) {
    __shared__ float Wb[64 * 64];     // reused weight buffer
    __shared__ float Xs[16 * 64];
    __shared__ float Ys[16 * 64];
    int tid = threadIdx.x;
    int row0 = blockIdx.x * 16;
    for (int i = tid; i < 4096; i += 256) Wb[i] = g_Wt[i];
    for (int i = tid; i < 1024; i += 256) {
        int rr = i >> 6, cc = i & 63;
        int nn = row0 + rr;
        Xs[i] = (nn < n) ? g_aggx[(size_t)nn * 64 + cc] : 0.f;
    }
    __syncthreads();
    int jr = (tid & 15) * 4;
    int rr = tid >> 4;
    const float* xr = Xs + rr * 64;
    {   // Y = relu(Xs @ W)
        float a0 = 0, a1 = 0, a2 = 0, a3 = 0;
#pragma unroll 8
        for (int k = 0; k < 64; k++) {
            float xv = xr[k];
            const float* wk = Wb + k * 64 + jr;
            a0 += xv * wk[0]; a1 += xv * wk[1]; a2 += xv * wk[2]; a3 += xv * wk[3];
        }
        Ys[rr * 64 + jr]     = fmaxf(a0, 0.f);
        Ys[rr * 64 + jr + 1] = fmaxf(a1, 0.f);
        Ys[rr * 64 + jr + 2] = fmaxf(a2, 0.f);
        Ys[rr * 64 + jr + 3] = fmaxf(a3, 0.f);
    }
    __syncthreads();
    for (int i = tid; i < 4096; i += 256) Wb[i] = w1[i];          // W1a
    __syncthreads();
    const float* yr = Ys + rr * 64;
    {   // A = Y @ W1a
        float a0 = 0, a1 = 0, a2 = 0, a3 = 0;
#pragma unroll 8
        for (int k = 0; k < 64; k++) {
            float yv = yr[k];
            const float* wk = Wb + k * 64 + jr;
            a0 += yv * wk[0]; a1 += yv * wk[1]; a2 += yv * wk[2]; a3 += yv * wk[3];
        }
        int nn = row0 + rr;
        if (nn < n) *(float4*)(g_A + (size_t)nn * 64 + jr) = make_float4(a0, a1, a2, a3);
    }
    __syncthreads();
    for (int i = tid; i < 4096; i += 256) Wb[i] = w1[4096 + i];   // W1b
    __syncthreads();
    {   // B = Y @ W1b
        float a0 = 0, a1 = 0, a2 = 0, a3 = 0;
#pragma unroll 8
        for (int k = 0; k < 64; k++) {
            float yv = yr[k];
            const float* wk = Wb + k * 64 + jr;
            a0 += yv * wk[0]; a1 += yv * wk[1]; a2 += yv * wk[2]; a3 += yv * wk[3];
        }
        int nn = row0 + rr;
        if (nn < n) *(float4*)(g_B + (size_t)nn * 64 + jr) = make_float4(a0, a1, a2, a3);
    }
}

// ---------------- k4 (PROFILED): Edge MLP (R3 body) + tail blocks zero cnt/aggx --------
__global__ void edge_mlp_zero_kernel(const int* __restrict__ ei,
                                     const float* __restrict__ ea,
                                     const float* __restrict__ w1,
                                     const float* __restrict__ b1,
                                     const float* __restrict__ w2,
                                     const float* __restrict__ b2,
                                     float* __restrict__ out, int E, int N, int EB) {
    if (blockIdx.x >= EB) {
        int i = (blockIdx.x - EB) * 256 + threadIdx.x;
        if (i < N * 16) ((float4*)g_aggx)[i] = make_float4(0.f, 0.f, 0.f, 0.f);
        if (i < N) g_cnt[i] = 0;
        return;
    }
    __shared__ float Wc[16 * 64];
    __shared__ float b1s[64];
    __shared__ float w2s[64];
    __shared__ float b2s;
    int tid = threadIdx.x;
    for (int i = tid; i < 1024; i += 256) Wc[i] = w1[8192 + i];   // rows 128..143
    if (tid < 64) { b1s[tid] = b1[tid]; w2s[tid] = w2[tid]; }
    if (tid == 0) b2s = b2[0];
    __syncthreads();
    int e = (blockIdx.x * 256 + tid) >> 5;
    int lane = tid & 31;
    if (e >= E) return;
    int src = ei[e];
    int dst = ei[E + e];
    float2 av = *(const float2*)(g_A + (size_t)src * 64 + 2 * lane);
    float2 bv = *(const float2*)(g_B + (size_t)dst * 64 + 2 * lane);
    float h0 = av.x + bv.x + b1s[2 * lane];
    float h1 = av.y + bv.y + b1s[2 * lane + 1];
    float eav = (lane < 16) ? ea[(size_t)e * 16 + lane] : 0.f;
#pragma unroll
    for (int k = 0; k < 16; k++) {
        float ek = __shfl_sync(0xffffffffu, eav, k);
        float2 wv = *(const float2*)(Wc + k * 64 + 2 * lane);
        h0 += ek * wv.x;
        h1 += ek * wv.y;
    }
    h0 = fmaxf(h0, 0.f);
    h1 = fmaxf(h1, 0.f);
    float p = h0 * w2s[2 * lane] + h1 * w2s[2 * lane + 1];
#pragma unroll
    for (int off = 16; off; off >>= 1) p += __shfl_xor_sync(0xffffffffu, p, off);
    if (lane == 0) out[e] = p + b2s;
}

extern "C" void kernel_launch(void* const* d_in, const int* in_sizes, int n_in,
                              void* d_out, int out_size) {
    const float* xs = (const float*)d_in[0];
    const int* ei = (const int*)d_in[1];            // int32 (JAX x64 disabled)
    const float* ea = (const float*)d_in[2];
    const float* init_w = (const float*)d_in[3];
    const float* w_ih = (const float*)d_in[4];
    const float* w_hh = (const float*)d_in[5];
    const float* b_ih = (const float*)d_in[6];
    const float* b_hh = (const float*)d_in[7];
    const float* w1 = (const float*)d_in[8];
    const float* b1 = (const float*)d_in[9];
    const float* w2 = (const float*)d_in[10];
    const float* b2 = (const float*)d_in[11];
    float* out = (float*)d_out;

    int N = in_sizes[0] / (5 * 64);
    int E = in_sizes[1] / 2;

    // k1: LSTM + in-degree histogram (g_cnt zeroed by previous call / load-time init)
    lstm_deg_kernel<<<64 + (E + 255) / 256, 256>>>(init_w, w_ih, w_hh, b_ih, b_hh, ei, E);
    // k2: scatter raw X (edges + self loops), aggx zeroed by previous call
    int items = E + N;
    scatter_x_kernel<<<(items * 16 + 255) / 256, 256>>>(xs + (size_t)4 * N * 64, ei, N, E);
    // k3: fused Y/A/B GEMMs
    gemm_AB_kernel<<<(N + 15) / 16, 256>>>(w1, N);
    // k4: per-edge MLP + logit (PROFILED) + tail zeroing for next call
    int EB = (E + 7) / 8;
    int ZB = (N * 16 + 255) / 256;
    edge_mlp_zero_kernel<<<EB + ZB, 256>>>(ei, ea, w1, b1, w2, b2, out, E, N, EB);
}